// round 16
// baseline (speedup 1.0000x reference)
#include <cuda_runtime.h>
#include <cuda_fp16.h>
#include <cstdint>

#define SQ   2048
#define ED   2048
#define NH   16
#define NG   32      // 2*H query/key heads
#define HDIM 64      // differential head dim
#define VDIM 128     // value head dim (2*HD)

static constexpr float LAMBDA_INIT = 0.78360576653162444f;
static constexpr int MWORDS = SQ * ED / 2;   // packed fp16x2 words per matrix

// ---- device scratch ----
// g_Q/g_K: packed fp16x2 [SQ][1024], word-permuted per qkperm (Q pre-scaled 0.125)
// g_V:     __half [NH][VDIM][SQ], seq word-permuted
// g_H16:   7 pre-converted operand matrices (query,key,value,Wq,Wk,Wv,Wo)
// g_Xh:    fp16 combined attention (GEMM A operand for the output projection)
__device__ float g_Q[SQ * ED];
__device__ float g_K[SQ * ED];
__device__ float g_V[SQ * ED];
__device__ float g_O[NG * SQ * VDIM];
__device__ unsigned g_H16[7 * MWORDS];
__device__ __half g_Xh[SQ * ED];
__device__ float g_lam;

// pack two fp32 -> fp16x2 {lo, hi}
__device__ __forceinline__ unsigned f2h2(float lo, float hi) {
    unsigned r;
    asm("cvt.rn.f16x2.f32 %0, %1, %2;" : "=r"(r) : "f"(hi), "f"(lo));
    return r;
}

__device__ __forceinline__ void mma_f16(float c[4], const unsigned a[4],
                                        unsigned b0, unsigned b1) {
    asm volatile(
        "mma.sync.aligned.m16n8k16.row.col.f32.f16.f16.f32 "
        "{%0,%1,%2,%3}, {%4,%5,%6,%7}, {%8,%9}, {%0,%1,%2,%3};"
        : "+f"(c[0]), "+f"(c[1]), "+f"(c[2]), "+f"(c[3])
        : "r"(a[0]), "r"(a[1]), "r"(a[2]), "r"(a[3]), "r"(b0), "r"(b1));
}

__device__ __forceinline__ uint32_t smem_u32(const void* p) {
    uint32_t a;
    asm("{ .reg .u64 t; cvta.to.shared.u64 t, %1; cvt.u32.u64 %0, t; }" : "=r"(a) : "l"(p));
    return a;
}

__device__ __forceinline__ void cp16(uint32_t dst, const void* src) {
    asm volatile("cp.async.cg.shared.global [%0], [%1], 16;" :: "r"(dst), "l"(src));
}

__device__ __forceinline__ int qkperm(int w) {
    int j = w & 15;
    return (w & ~15) | (4 * (j & 3) + 2 * ((j >> 3) & 1) + ((j >> 2) & 1));
}

// ============================================================================
// cvt: fp32 matrix -> packed fp16x2 words (same cvt.rn rounding as before).
// grid (SQ*ED/4/256, 7), 256 threads.
// ============================================================================
__global__ __launch_bounds__(256) void cvt_kernel(
    const float* __restrict__ s0, const float* __restrict__ s1,
    const float* __restrict__ s2, const float* __restrict__ s3,
    const float* __restrict__ s4, const float* __restrict__ s5,
    const float* __restrict__ s6)
{
    const float* srcs[7] = { s0, s1, s2, s3, s4, s5, s6 };
    const float* s = srcs[blockIdx.y];
    unsigned* d = g_H16 + blockIdx.y * MWORDS;
    int i = blockIdx.x * 256 + threadIdx.x;           // float4 index
    float4 v = *(const float4*)(s + i * 4);
    *(uint2*)(d + i * 2) = make_uint2(f2h2(v.x, v.y), f2h2(v.z, v.w));
}

// ============================================================================
// FP16 GEMM (NT), cp.async double-buffered fp16 operands, 1 sync/ktile.
// 128x128x32 tile, 8 warps, m16n8k16. a_sel: 0..2 = g_H16 seg (q/k/v),
// 3 = g_Xh. w_sel: 0..3 = g_H16 seg 3..6 (Wq/Wk/Wv/Wo).
// c_tag: 0 -> Cext fp32; 1/2/3 -> g_Q/g_K/g_V permuted fp16 (as R15).
// ============================================================================
__global__ __launch_bounds__(256, 2) void gemm_nt(float* __restrict__ Cext,
                                                  int a_sel, int w_sel, int c_tag)
{
    __shared__ unsigned As[2][128][20];
    __shared__ unsigned Bs[2][128][20];

    const unsigned* Aw = (a_sel < 3) ? (g_H16 + a_sel * MWORDS)
                                     : (const unsigned*)g_Xh;
    const unsigned* Ww = g_H16 + (3 + w_sel) * MWORDS;

    const int t    = threadIdx.x;
    const int m0   = blockIdx.y * 128;
    const int n0   = blockIdx.x * 128;
    const int wid  = t >> 5;
    const int lane = t & 31;
    const int wm   = (wid >> 2) * 64;
    const int wn   = (wid & 3) * 32;
    const int grp  = lane >> 2;
    const int qid  = lane & 3;

    const uint32_t sA = smem_u32(As);
    const uint32_t sB = smem_u32(Bs);

    // fill(kt): stage 128 rows x 16 words of A and W into buffer kt&1
    auto fill = [&](int kt2) {
        const int buf = kt2 & 1;
        #pragma unroll
        for (int j = 0; j < 2; j++) {
            int idx = t + 256 * j;                 // 512 chunks: r=idx>>2, c=idx&3
            int r = idx >> 2, c = idx & 3;
            uint32_t so = (uint32_t)(buf * 2560 + r * 20 + c * 4) * 4u;
            cp16(sA + so, Aw + (m0 + r) * 1024 + kt2 * 16 + c * 4);
            cp16(sB + so, Ww + (n0 + r) * 1024 + kt2 * 16 + c * 4);
        }
        asm volatile("cp.async.commit_group;" ::: "memory");
    };

    float acc[4][4][4];
    #pragma unroll
    for (int mi = 0; mi < 4; mi++)
        #pragma unroll
        for (int ni = 0; ni < 4; ni++)
            #pragma unroll
            for (int x = 0; x < 4; x++) acc[mi][ni][x] = 0.f;

    const int NT = ED / 32;  // 64
    fill(0);

    for (int kt = 0; kt < NT; kt++) {
        asm volatile("cp.async.wait_group 0;" ::: "memory");
        __syncthreads();
        if (kt + 1 < NT) fill(kt + 1);

        const int cur = kt & 1;
        #pragma unroll
        for (int s = 0; s < 2; s++) {
            unsigned af[4][4], bf[4][2];
            #pragma unroll
            for (int mi = 0; mi < 4; mi++) {
                int r = wm + mi * 16 + grp;
                af[mi][0] = As[cur][r][8 * s + qid];
                af[mi][1] = As[cur][r + 8][8 * s + qid];
                af[mi][2] = As[cur][r][8 * s + qid + 4];
                af[mi][3] = As[cur][r + 8][8 * s + qid + 4];
            }
            #pragma unroll
            for (int ni = 0; ni < 4; ni++) {
                int rn = wn + ni * 8 + grp;
                bf[ni][0] = Bs[cur][rn][8 * s + qid];
                bf[ni][1] = Bs[cur][rn][8 * s + qid + 4];
            }
            #pragma unroll
            for (int mi = 0; mi < 4; mi++)
                #pragma unroll
                for (int ni = 0; ni < 4; ni++)
                    mma_f16(acc[mi][ni], af[mi], bf[ni][0], bf[ni][1]);
        }
    }

    if (c_tag == 0) {
        #pragma unroll
        for (int mi = 0; mi < 4; mi++)
            #pragma unroll
            for (int ni = 0; ni < 4; ni++) {
                int row = m0 + wm + mi * 16 + grp;
                int col = n0 + wn + ni * 8 + 2 * qid;
                *(float2*)&Cext[row * ED + col]       = make_float2(acc[mi][ni][0], acc[mi][ni][1]);
                *(float2*)&Cext[(row + 8) * ED + col] = make_float2(acc[mi][ni][2], acc[mi][ni][3]);
            }
    } else if (c_tag == 3) {
        __half* gVh = (__half*)g_V;
        #pragma unroll
        for (int mi = 0; mi < 4; mi++)
            #pragma unroll
            for (int ni = 0; ni < 4; ni++) {
                int row0 = m0 + wm + mi * 16 + grp;
                int col0 = n0 + wn + ni * 8 + 2 * qid;
                #pragma unroll
                for (int x = 0; x < 4; x++) {
                    int row = row0 + ((x >> 1) << 3);
                    int col = col0 + (x & 1);
                    int wp = qkperm(row >> 1);
                    gVh[(col >> 7) * (VDIM * SQ) + (col & 127) * SQ + 2 * wp + (row & 1)] =
                        __float2half_rn(acc[mi][ni][x]);
                }
            }
    } else {
        unsigned* Ch = (unsigned*)((c_tag == 1) ? g_Q : g_K);
        const float esc = (c_tag == 1) ? 0.125f : 1.0f;
        #pragma unroll
        for (int mi = 0; mi < 4; mi++)
            #pragma unroll
            for (int ni = 0; ni < 4; ni++) {
                int row = m0 + wm + mi * 16 + grp;
                int col = n0 + wn + ni * 8 + 2 * qid;
                int wp = qkperm(col >> 1);
                Ch[row * 1024 + wp] =
                    f2h2(acc[mi][ni][0] * esc, acc[mi][ni][1] * esc);
                Ch[(row + 8) * 1024 + wp] =
                    f2h2(acc[mi][ni][2] * esc, acc[mi][ni][3] * esc);
            }
    }
}

// ============================================================================
// lambda_full
// ============================================================================
__global__ void lam_kernel(const float* __restrict__ lq1, const float* __restrict__ lk1,
                           const float* __restrict__ lq2, const float* __restrict__ lk2)
{
    int lane = threadIdx.x;  // 64 threads
    float p1 = lq1[lane] * lk1[lane];
    float p2 = lq2[lane] * lk2[lane];
    #pragma unroll
    for (int o = 16; o > 0; o >>= 1) {
        p1 += __shfl_xor_sync(0xffffffffu, p1, o);
        p2 += __shfl_xor_sync(0xffffffffu, p2, o);
    }
    __shared__ float s1w[2], s2w[2];
    if ((lane & 31) == 0) { s1w[lane >> 5] = p1; s2w[lane >> 5] = p2; }
    __syncthreads();
    if (lane == 0)
        g_lam = expf(s1w[0] + s1w[1]) - expf(s2w[0] + s2w[1]) + LAMBDA_INIT;
}

// ============================================================================
// FP16 flash attention — unchanged from R15 (201.7 us, proven).
// ============================================================================
static constexpr int PTC = 48;
static constexpr int KWORDS = 64 * PTC;
static constexpr int VWORDS = 128 * PTC;
static constexpr int ATTN_SMEM = (128 * PTC + 2 * KWORDS + 2 * VWORDS) * 4 + SQ * 4;

__global__ __launch_bounds__(256, 1) void attn_kernel(const unsigned char* __restrict__ mask)
{
    extern __shared__ unsigned smu[];
    unsigned* Qs = smu;
    unsigned* Ks = smu + 128 * PTC;
    unsigned* Vs = Ks + 2 * KWORDS;
    float* Msall = (float*)(Vs + 2 * VWORDS);

    const int g    = blockIdx.y;
    const int h    = g >> 1;
    const int q0   = blockIdx.x * 128;
    const int t    = threadIdx.x;
    const int lane = t & 31;
    const int grp  = lane >> 2;
    const int qid  = lane & 3;
    const int wq   = (t >> 5) * 16;

    const unsigned* gQw = (const unsigned*)g_Q;
    const unsigned* gKw = (const unsigned*)g_K;
    const unsigned* gVw = (const unsigned*)g_V;

    const uint32_t sQ = smem_u32(Qs);
    const uint32_t sK = smem_u32(Ks);
    const uint32_t sV = smem_u32(Vs);

    #pragma unroll
    for (int j = 0; j < 4; j++) {
        int idx = t + 256 * j;
        int r = idx >> 3, c4 = idx & 7;
        cp16(sQ + (uint32_t)(r * PTC + c4 * 4) * 4u,
             gQw + (q0 + r) * 1024 + g * 32 + c4 * 4);
    }
    asm volatile("cp.async.commit_group;" ::: "memory");

    auto fill = [&](int kt2) {
        const int b = kt2 & 1;
        const uint32_t kb = sK + (uint32_t)(b * KWORDS) * 4u;
        const uint32_t vb = sV + (uint32_t)(b * VWORDS) * 4u;
        const int row0 = kt2 * 64;
        #pragma unroll
        for (int j = 0; j < 2; j++) {
            int idx = t + 256 * j;
            int r = idx >> 3, c4 = idx & 7;
            cp16(kb + (uint32_t)(r * PTC + c4 * 4) * 4u,
                 gKw + (row0 + r) * 1024 + g * 32 + c4 * 4);
        }
        #pragma unroll
        for (int j = 0; j < 4; j++) {
            int idx = t + 256 * j;
            int c = idx >> 3, s4 = idx & 7;
            cp16(vb + (uint32_t)(c * PTC + s4 * 4) * 4u,
                 gVw + h * (VDIM * 1024) + c * 1024 + kt2 * 32 + s4 * 4);
        }
        asm volatile("cp.async.commit_group;" ::: "memory");
    };

    fill(0);

    for (int i = t; i < SQ; i += 256)
        Msall[i] = mask[i] ? -1e30f : 0.f;

    asm volatile("cp.async.wait_group 1;" ::: "memory");
    __syncthreads();

    unsigned qf[4][4];
    #pragma unroll
    for (int blk = 0; blk < 2; blk++) {
        uint4 a = *(const uint4*)&Qs[(wq + grp) * PTC + 16 * blk + 4 * qid];
        uint4 b = *(const uint4*)&Qs[(wq + grp + 8) * PTC + 16 * blk + 4 * qid];
        qf[2 * blk][0] = a.x; qf[2 * blk][1] = b.x; qf[2 * blk][2] = a.y; qf[2 * blk][3] = b.y;
        qf[2 * blk + 1][0] = a.z; qf[2 * blk + 1][1] = b.z;
        qf[2 * blk + 1][2] = a.w; qf[2 * blk + 1][3] = b.w;
    }

    float of[16][4];
    #pragma unroll
    for (int n = 0; n < 16; n++)
        #pragma unroll
        for (int x = 0; x < 4; x++) of[n][x] = 0.f;
    float m0 = -1e30f, m1 = -1e30f, l0 = 0.f, l1 = 0.f;

    const int NT = SQ / 64;
    for (int kt = 0; kt < NT; kt++) {
        asm volatile("cp.async.wait_group 0;" ::: "memory");
        __syncthreads();
        if (kt + 1 < NT) fill(kt + 1);

        const unsigned* Kb = Ks + (kt & 1) * KWORDS;
        const unsigned* Vb = Vs + (kt & 1) * VWORDS;
        const float*    Mb = Msall + kt * 64;

        float sc[8][4];
        #pragma unroll
        for (int n = 0; n < 8; n++)
            #pragma unroll
            for (int x = 0; x < 4; x++) sc[n][x] = 0.f;
        #pragma unroll
        for (int blk = 0; blk < 2; blk++) {
            #pragma unroll
            for (int nb = 0; nb < 8; nb++) {
                uint4 kv = *(const uint4*)&Kb[(8 * nb + grp) * PTC + 16 * blk + 4 * qid];
                mma_f16(sc[nb], qf[2 * blk], kv.x, kv.y);
                mma_f16(sc[nb], qf[2 * blk + 1], kv.z, kv.w);
            }
        }
        #pragma unroll
        for (int n = 0; n < 8; n++) {
            float a0 = Mb[8 * n + 2 * qid], a1 = Mb[8 * n + 2 * qid + 1];
            sc[n][0] += a0; sc[n][1] += a1; sc[n][2] += a0; sc[n][3] += a1;
        }

        float mx0 = -1e30f, mx1 = -1e30f;
        #pragma unroll
        for (int n = 0; n < 8; n++) {
            mx0 = fmaxf(mx0, fmaxf(sc[n][0], sc[n][1]));
            mx1 = fmaxf(mx1, fmaxf(sc[n][2], sc[n][3]));
        }
        mx0 = fmaxf(mx0, __shfl_xor_sync(0xffffffffu, mx0, 1));
        mx0 = fmaxf(mx0, __shfl_xor_sync(0xffffffffu, mx0, 2));
        mx1 = fmaxf(mx1, __shfl_xor_sync(0xffffffffu, mx1, 1));
        mx1 = fmaxf(mx1, __shfl_xor_sync(0xffffffffu, mx1, 2));
        float mn0 = fmaxf(m0, mx0), mn1 = fmaxf(m1, mx1);
        float sum0 = 0.f, sum1 = 0.f;
        #pragma unroll
        for (int n = 0; n < 8; n++) {
            sc[n][0] = __expf(sc[n][0] - mn0); sum0 += sc[n][0];
            sc[n][1] = __expf(sc[n][1] - mn0); sum0 += sc[n][1];
            sc[n][2] = __expf(sc[n][2] - mn1); sum1 += sc[n][2];
            sc[n][3] = __expf(sc[n][3] - mn1); sum1 += sc[n][3];
        }
        sum0 += __shfl_xor_sync(0xffffffffu, sum0, 1);
        sum0 += __shfl_xor_sync(0xffffffffu, sum0, 2);
        sum1 += __shfl_xor_sync(0xffffffffu, sum1, 1);
        sum1 += __shfl_xor_sync(0xffffffffu, sum1, 2);
        float f0 = __expf(m0 - mn0), f1 = __expf(m1 - mn1);
        l0 = l0 * f0 + sum0; l1 = l1 * f1 + sum1;
        m0 = mn0; m1 = mn1;
        #pragma unroll
        for (int n = 0; n < 16; n++) {
            of[n][0] *= f0; of[n][1] *= f0; of[n][2] *= f1; of[n][3] *= f1;
        }

        unsigned pa[4][4];
        #pragma unroll
        for (int s = 0; s < 4; s++) {
            pa[s][0] = f2h2(sc[2 * s][0], sc[2 * s][1]);
            pa[s][1] = f2h2(sc[2 * s][2], sc[2 * s][3]);
            pa[s][2] = f2h2(sc[2 * s + 1][0], sc[2 * s + 1][1]);
            pa[s][3] = f2h2(sc[2 * s + 1][2], sc[2 * s + 1][3]);
        }

        #pragma unroll
        for (int blk = 0; blk < 2; blk++) {
            #pragma unroll
            for (int nv = 0; nv < 16; nv++) {
                uint4 vv = *(const uint4*)&Vb[(8 * nv + grp) * PTC + 16 * blk + 4 * qid];
                mma_f16(of[nv], pa[2 * blk], vv.x, vv.y);
                mma_f16(of[nv], pa[2 * blk + 1], vv.z, vv.w);
            }
        }
    }

    float r0 = 1.f / l0, r1 = 1.f / l1;
    #pragma unroll
    for (int n = 0; n < 16; n++) {
        int row = q0 + wq + grp, col = 8 * n + 2 * qid;
        *(float2*)&g_O[(g * SQ + row) * VDIM + col]     =
            make_float2(of[n][0] * r0, of[n][1] * r0);
        *(float2*)&g_O[(g * SQ + row + 8) * VDIM + col] =
            make_float2(of[n][2] * r1, of[n][3] * r1);
    }
}

// ============================================================================
// Epilogue: x = O[2h]-lam*O[2h+1]; RMSNorm; *subg*(1-lam_init); store fp16
// (fp16 rounding here == the rounding the old GEMM staging applied to g_X).
// ============================================================================
__global__ __launch_bounds__(128) void epi_kernel(const float* __restrict__ subg)
{
    const int s = blockIdx.x, h = blockIdx.y, d = threadIdx.x;
    const float lam = g_lam;
    float a = g_O[((2 * h) * SQ + s) * VDIM + d];
    float b = g_O[((2 * h + 1) * SQ + s) * VDIM + d];
    float x = a - lam * b;

    float v = x * x;
    #pragma unroll
    for (int o = 16; o > 0; o >>= 1) v += __shfl_xor_sync(0xffffffffu, v, o);
    __shared__ float ws[4];
    if ((d & 31) == 0) ws[d >> 5] = v;
    __syncthreads();
    float tot = ws[0] + ws[1] + ws[2] + ws[3];
    float rms = rsqrtf(tot * (1.f / 128.f) + 1e-5f);

    g_Xh[s * ED + h * VDIM + d] =
        __float2half_rn(x * rms * subg[d] * (1.f - LAMBDA_INIT));
}

// ============================================================================
// launch — cvt first; 4th launch = gemm (value) lands in the ncu slot.
// ============================================================================
extern "C" void kernel_launch(void* const* d_in, const int* in_sizes, int n_in,
                              void* d_out, int out_size)
{
    (void)in_sizes; (void)n_in; (void)out_size;
    const float* query = (const float*)d_in[0];
    const float* key   = (const float*)d_in[1];
    const float* value = (const float*)d_in[2];
    const unsigned char* mask = (const unsigned char*)d_in[4];
    const float* Wq  = (const float*)d_in[5];
    const float* Wk  = (const float*)d_in[6];
    const float* Wv  = (const float*)d_in[7];
    const float* Wo  = (const float*)d_in[8];
    const float* lq1 = (const float*)d_in[9];
    const float* lk1 = (const float*)d_in[10];
    const float* lq2 = (const float*)d_in[11];
    const float* lk2 = (const float*)d_in[12];
    const float* subg = (const float*)d_in[13];
    float* out = (float*)d_out;

    cudaFuncSetAttribute(attn_kernel, cudaFuncAttributeMaxDynamicSharedMemorySize, ATTN_SMEM);

    dim3 gblk(16, 16);
    cvt_kernel<<<dim3(SQ * ED / 4 / 256, 7), 256>>>(query, key, value, Wq, Wk, Wv, Wo);
    gemm_nt<<<gblk, 256>>>(nullptr, 0, 0, 1);   // Q = query * Wq
    gemm_nt<<<gblk, 256>>>(nullptr, 1, 1, 2);   // K = key   * Wk
    gemm_nt<<<gblk, 256>>>(nullptr, 2, 2, 3);   // V = value * Wv
    attn_kernel<<<dim3(16, 32), 256, ATTN_SMEM>>>(mask);
    lam_kernel<<<1, 64>>>(lq1, lk1, lq2, lk2);
    epi_kernel<<<dim3(SQ, NH), 128>>>(subg);
    gemm_nt<<<gblk, 256>>>(out, 3, 3, 0);       // out = X * Wo
}

// round 17
// speedup vs baseline: 1.0464x; 1.0464x over previous
#include <cuda_runtime.h>
#include <cuda_fp16.h>
#include <cstdint>

#define SQ   2048
#define ED   2048
#define NH   16
#define NG   32      // 2*H query/key heads
#define HDIM 64      // differential head dim
#define VDIM 128     // value head dim (2*HD)

static constexpr float LAMBDA_INIT = 0.78360576653162444f;
static constexpr int MWORDS = SQ * ED / 2;   // packed fp16x2 words per matrix

// ---- device scratch ----
__device__ float g_Q[SQ * ED];
__device__ float g_K[SQ * ED];
__device__ float g_V[SQ * ED];
__device__ float g_O[NG * SQ * VDIM];
__device__ unsigned g_H16[7 * MWORDS];
__device__ __half g_Xh[SQ * ED];
__device__ float g_lam;

__device__ __forceinline__ unsigned f2h2(float lo, float hi) {
    unsigned r;
    asm("cvt.rn.f16x2.f32 %0, %1, %2;" : "=r"(r) : "f"(hi), "f"(lo));
    return r;
}

__device__ __forceinline__ void mma_f16(float c[4], const unsigned a[4],
                                        unsigned b0, unsigned b1) {
    asm volatile(
        "mma.sync.aligned.m16n8k16.row.col.f32.f16.f16.f32 "
        "{%0,%1,%2,%3}, {%4,%5,%6,%7}, {%8,%9}, {%0,%1,%2,%3};"
        : "+f"(c[0]), "+f"(c[1]), "+f"(c[2]), "+f"(c[3])
        : "r"(a[0]), "r"(a[1]), "r"(a[2]), "r"(a[3]), "r"(b0), "r"(b1));
}

__device__ __forceinline__ uint32_t smem_u32(const void* p) {
    uint32_t a;
    asm("{ .reg .u64 t; cvta.to.shared.u64 t, %1; cvt.u32.u64 %0, t; }" : "=r"(a) : "l"(p));
    return a;
}

__device__ __forceinline__ void cp16(uint32_t dst, const void* src) {
    asm volatile("cp.async.cg.shared.global [%0], [%1], 16;" :: "r"(dst), "l"(src));
}

__device__ __forceinline__ int qkperm(int w) {
    int j = w & 15;
    return (w & ~15) | (4 * (j & 3) + 2 * ((j >> 3) & 1) + ((j >> 2) & 1));
}

// ============================================================================
// cvt: fp32 matrix -> packed fp16x2 words
// ============================================================================
__global__ __launch_bounds__(256) void cvt_kernel(
    const float* __restrict__ s0, const float* __restrict__ s1,
    const float* __restrict__ s2, const float* __restrict__ s3,
    const float* __restrict__ s4, const float* __restrict__ s5,
    const float* __restrict__ s6)
{
    const float* srcs[7] = { s0, s1, s2, s3, s4, s5, s6 };
    const float* s = srcs[blockIdx.y];
    unsigned* d = g_H16 + blockIdx.y * MWORDS;
    int i = blockIdx.x * 256 + threadIdx.x;
    float4 v = *(const float4*)(s + i * 4);
    *(uint2*)(d + i * 2) = make_uint2(f2h2(v.x, v.y), f2h2(v.z, v.w));
}

// ============================================================================
// FP16 GEMM (NT), cp.async double-buffered, 1 sync/ktile.
// fused==1: blockIdx.z = 0/1/2 selects (A=q/k/v, W=Wq/Wk/Wv, C=g_Q/g_K/g_V).
// fused==0: a_sel/w_sel/c_tag args used (output projection / generic).
// ============================================================================
__global__ __launch_bounds__(256, 2) void gemm_nt(float* __restrict__ Cext,
                                                  int a_sel, int w_sel, int c_tag,
                                                  int fused)
{
    __shared__ unsigned As[2][128][20];
    __shared__ unsigned Bs[2][128][20];

    if (fused) { a_sel = blockIdx.z; w_sel = blockIdx.z; c_tag = blockIdx.z + 1; }

    const unsigned* Aw = (a_sel < 3) ? (g_H16 + a_sel * MWORDS)
                                     : (const unsigned*)g_Xh;
    const unsigned* Ww = g_H16 + (3 + w_sel) * MWORDS;

    const int t    = threadIdx.x;
    const int m0   = blockIdx.y * 128;
    const int n0   = blockIdx.x * 128;
    const int wid  = t >> 5;
    const int lane = t & 31;
    const int wm   = (wid >> 2) * 64;
    const int wn   = (wid & 3) * 32;
    const int grp  = lane >> 2;
    const int qid  = lane & 3;

    const uint32_t sA = smem_u32(As);
    const uint32_t sB = smem_u32(Bs);

    auto fill = [&](int kt2) {
        const int buf = kt2 & 1;
        #pragma unroll
        for (int j = 0; j < 2; j++) {
            int idx = t + 256 * j;
            int r = idx >> 2, c = idx & 3;
            uint32_t so = (uint32_t)(buf * 2560 + r * 20 + c * 4) * 4u;
            cp16(sA + so, Aw + (m0 + r) * 1024 + kt2 * 16 + c * 4);
            cp16(sB + so, Ww + (n0 + r) * 1024 + kt2 * 16 + c * 4);
        }
        asm volatile("cp.async.commit_group;" ::: "memory");
    };

    float acc[4][4][4];
    #pragma unroll
    for (int mi = 0; mi < 4; mi++)
        #pragma unroll
        for (int ni = 0; ni < 4; ni++)
            #pragma unroll
            for (int x = 0; x < 4; x++) acc[mi][ni][x] = 0.f;

    const int NT = ED / 32;  // 64
    fill(0);

    for (int kt = 0; kt < NT; kt++) {
        asm volatile("cp.async.wait_group 0;" ::: "memory");
        __syncthreads();
        if (kt + 1 < NT) fill(kt + 1);

        const int cur = kt & 1;
        #pragma unroll
        for (int s = 0; s < 2; s++) {
            unsigned af[4][4], bf[4][2];
            #pragma unroll
            for (int mi = 0; mi < 4; mi++) {
                int r = wm + mi * 16 + grp;
                af[mi][0] = As[cur][r][8 * s + qid];
                af[mi][1] = As[cur][r + 8][8 * s + qid];
                af[mi][2] = As[cur][r][8 * s + qid + 4];
                af[mi][3] = As[cur][r + 8][8 * s + qid + 4];
            }
            #pragma unroll
            for (int ni = 0; ni < 4; ni++) {
                int rn = wn + ni * 8 + grp;
                bf[ni][0] = Bs[cur][rn][8 * s + qid];
                bf[ni][1] = Bs[cur][rn][8 * s + qid + 4];
            }
            #pragma unroll
            for (int mi = 0; mi < 4; mi++)
                #pragma unroll
                for (int ni = 0; ni < 4; ni++)
                    mma_f16(acc[mi][ni], af[mi], bf[ni][0], bf[ni][1]);
        }
    }

    if (c_tag == 0) {
        #pragma unroll
        for (int mi = 0; mi < 4; mi++)
            #pragma unroll
            for (int ni = 0; ni < 4; ni++) {
                int row = m0 + wm + mi * 16 + grp;
                int col = n0 + wn + ni * 8 + 2 * qid;
                *(float2*)&Cext[row * ED + col]       = make_float2(acc[mi][ni][0], acc[mi][ni][1]);
                *(float2*)&Cext[(row + 8) * ED + col] = make_float2(acc[mi][ni][2], acc[mi][ni][3]);
            }
    } else if (c_tag == 3) {
        __half* gVh = (__half*)g_V;
        #pragma unroll
        for (int mi = 0; mi < 4; mi++)
            #pragma unroll
            for (int ni = 0; ni < 4; ni++) {
                int row0 = m0 + wm + mi * 16 + grp;
                int col0 = n0 + wn + ni * 8 + 2 * qid;
                #pragma unroll
                for (int x = 0; x < 4; x++) {
                    int row = row0 + ((x >> 1) << 3);
                    int col = col0 + (x & 1);
                    int wp = qkperm(row >> 1);
                    gVh[(col >> 7) * (VDIM * SQ) + (col & 127) * SQ + 2 * wp + (row & 1)] =
                        __float2half_rn(acc[mi][ni][x]);
                }
            }
    } else {
        unsigned* Ch = (unsigned*)((c_tag == 1) ? g_Q : g_K);
        const float esc = (c_tag == 1) ? 0.125f : 1.0f;
        #pragma unroll
        for (int mi = 0; mi < 4; mi++)
            #pragma unroll
            for (int ni = 0; ni < 4; ni++) {
                int row = m0 + wm + mi * 16 + grp;
                int col = n0 + wn + ni * 8 + 2 * qid;
                int wp = qkperm(col >> 1);
                Ch[row * 1024 + wp] =
                    f2h2(acc[mi][ni][0] * esc, acc[mi][ni][1] * esc);
                Ch[(row + 8) * 1024 + wp] =
                    f2h2(acc[mi][ni][2] * esc, acc[mi][ni][3] * esc);
            }
    }
}

// ============================================================================
// lambda_full
// ============================================================================
__global__ void lam_kernel(const float* __restrict__ lq1, const float* __restrict__ lk1,
                           const float* __restrict__ lq2, const float* __restrict__ lk2)
{
    int lane = threadIdx.x;  // 64 threads
    float p1 = lq1[lane] * lk1[lane];
    float p2 = lq2[lane] * lk2[lane];
    #pragma unroll
    for (int o = 16; o > 0; o >>= 1) {
        p1 += __shfl_xor_sync(0xffffffffu, p1, o);
        p2 += __shfl_xor_sync(0xffffffffu, p2, o);
    }
    __shared__ float s1w[2], s2w[2];
    if ((lane & 31) == 0) { s1w[lane >> 5] = p1; s2w[lane >> 5] = p2; }
    __syncthreads();
    if (lane == 0)
        g_lam = expf(s1w[0] + s1w[1]) - expf(s2w[0] + s2w[1]) + LAMBDA_INIT;
}

// ============================================================================
// FP16 flash attention — unchanged from R15 (201.7 us, proven).
// ============================================================================
static constexpr int PTC = 48;
static constexpr int KWORDS = 64 * PTC;
static constexpr int VWORDS = 128 * PTC;
static constexpr int ATTN_SMEM = (128 * PTC + 2 * KWORDS + 2 * VWORDS) * 4 + SQ * 4;

__global__ __launch_bounds__(256, 1) void attn_kernel(const unsigned char* __restrict__ mask)
{
    extern __shared__ unsigned smu[];
    unsigned* Qs = smu;
    unsigned* Ks = smu + 128 * PTC;
    unsigned* Vs = Ks + 2 * KWORDS;
    float* Msall = (float*)(Vs + 2 * VWORDS);

    const int g    = blockIdx.y;
    const int h    = g >> 1;
    const int q0   = blockIdx.x * 128;
    const int t    = threadIdx.x;
    const int lane = t & 31;
    const int grp  = lane >> 2;
    const int qid  = lane & 3;
    const int wq   = (t >> 5) * 16;

    const unsigned* gQw = (const unsigned*)g_Q;
    const unsigned* gKw = (const unsigned*)g_K;
    const unsigned* gVw = (const unsigned*)g_V;

    const uint32_t sQ = smem_u32(Qs);
    const uint32_t sK = smem_u32(Ks);
    const uint32_t sV = smem_u32(Vs);

    #pragma unroll
    for (int j = 0; j < 4; j++) {
        int idx = t + 256 * j;
        int r = idx >> 3, c4 = idx & 7;
        cp16(sQ + (uint32_t)(r * PTC + c4 * 4) * 4u,
             gQw + (q0 + r) * 1024 + g * 32 + c4 * 4);
    }
    asm volatile("cp.async.commit_group;" ::: "memory");

    auto fill = [&](int kt2) {
        const int b = kt2 & 1;
        const uint32_t kb = sK + (uint32_t)(b * KWORDS) * 4u;
        const uint32_t vb = sV + (uint32_t)(b * VWORDS) * 4u;
        const int row0 = kt2 * 64;
        #pragma unroll
        for (int j = 0; j < 2; j++) {
            int idx = t + 256 * j;
            int r = idx >> 3, c4 = idx & 7;
            cp16(kb + (uint32_t)(r * PTC + c4 * 4) * 4u,
                 gKw + (row0 + r) * 1024 + g * 32 + c4 * 4);
        }
        #pragma unroll
        for (int j = 0; j < 4; j++) {
            int idx = t + 256 * j;
            int c = idx >> 3, s4 = idx & 7;
            cp16(vb + (uint32_t)(c * PTC + s4 * 4) * 4u,
                 gVw + h * (VDIM * 1024) + c * 1024 + kt2 * 32 + s4 * 4);
        }
        asm volatile("cp.async.commit_group;" ::: "memory");
    };

    fill(0);

    for (int i = t; i < SQ; i += 256)
        Msall[i] = mask[i] ? -1e30f : 0.f;

    asm volatile("cp.async.wait_group 1;" ::: "memory");
    __syncthreads();

    unsigned qf[4][4];
    #pragma unroll
    for (int blk = 0; blk < 2; blk++) {
        uint4 a = *(const uint4*)&Qs[(wq + grp) * PTC + 16 * blk + 4 * qid];
        uint4 b = *(const uint4*)&Qs[(wq + grp + 8) * PTC + 16 * blk + 4 * qid];
        qf[2 * blk][0] = a.x; qf[2 * blk][1] = b.x; qf[2 * blk][2] = a.y; qf[2 * blk][3] = b.y;
        qf[2 * blk + 1][0] = a.z; qf[2 * blk + 1][1] = b.z;
        qf[2 * blk + 1][2] = a.w; qf[2 * blk + 1][3] = b.w;
    }

    float of[16][4];
    #pragma unroll
    for (int n = 0; n < 16; n++)
        #pragma unroll
        for (int x = 0; x < 4; x++) of[n][x] = 0.f;
    float m0 = -1e30f, m1 = -1e30f, l0 = 0.f, l1 = 0.f;

    const int NT = SQ / 64;
    for (int kt = 0; kt < NT; kt++) {
        asm volatile("cp.async.wait_group 0;" ::: "memory");
        __syncthreads();
        if (kt + 1 < NT) fill(kt + 1);

        const unsigned* Kb = Ks + (kt & 1) * KWORDS;
        const unsigned* Vb = Vs + (kt & 1) * VWORDS;
        const float*    Mb = Msall + kt * 64;

        float sc[8][4];
        #pragma unroll
        for (int n = 0; n < 8; n++)
            #pragma unroll
            for (int x = 0; x < 4; x++) sc[n][x] = 0.f;
        #pragma unroll
        for (int blk = 0; blk < 2; blk++) {
            #pragma unroll
            for (int nb = 0; nb < 8; nb++) {
                uint4 kv = *(const uint4*)&Kb[(8 * nb + grp) * PTC + 16 * blk + 4 * qid];
                mma_f16(sc[nb], qf[2 * blk], kv.x, kv.y);
                mma_f16(sc[nb], qf[2 * blk + 1], kv.z, kv.w);
            }
        }
        #pragma unroll
        for (int n = 0; n < 8; n++) {
            float a0 = Mb[8 * n + 2 * qid], a1 = Mb[8 * n + 2 * qid + 1];
            sc[n][0] += a0; sc[n][1] += a1; sc[n][2] += a0; sc[n][3] += a1;
        }

        float mx0 = -1e30f, mx1 = -1e30f;
        #pragma unroll
        for (int n = 0; n < 8; n++) {
            mx0 = fmaxf(mx0, fmaxf(sc[n][0], sc[n][1]));
            mx1 = fmaxf(mx1, fmaxf(sc[n][2], sc[n][3]));
        }
        mx0 = fmaxf(mx0, __shfl_xor_sync(0xffffffffu, mx0, 1));
        mx0 = fmaxf(mx0, __shfl_xor_sync(0xffffffffu, mx0, 2));
        mx1 = fmaxf(mx1, __shfl_xor_sync(0xffffffffu, mx1, 1));
        mx1 = fmaxf(mx1, __shfl_xor_sync(0xffffffffu, mx1, 2));
        float mn0 = fmaxf(m0, mx0), mn1 = fmaxf(m1, mx1);
        float sum0 = 0.f, sum1 = 0.f;
        #pragma unroll
        for (int n = 0; n < 8; n++) {
            sc[n][0] = __expf(sc[n][0] - mn0); sum0 += sc[n][0];
            sc[n][1] = __expf(sc[n][1] - mn0); sum0 += sc[n][1];
            sc[n][2] = __expf(sc[n][2] - mn1); sum1 += sc[n][2];
            sc[n][3] = __expf(sc[n][3] - mn1); sum1 += sc[n][3];
        }
        sum0 += __shfl_xor_sync(0xffffffffu, sum0, 1);
        sum0 += __shfl_xor_sync(0xffffffffu, sum0, 2);
        sum1 += __shfl_xor_sync(0xffffffffu, sum1, 1);
        sum1 += __shfl_xor_sync(0xffffffffu, sum1, 2);
        float f0 = __expf(m0 - mn0), f1 = __expf(m1 - mn1);
        l0 = l0 * f0 + sum0; l1 = l1 * f1 + sum1;
        m0 = mn0; m1 = mn1;
        #pragma unroll
        for (int n = 0; n < 16; n++) {
            of[n][0] *= f0; of[n][1] *= f0; of[n][2] *= f1; of[n][3] *= f1;
        }

        unsigned pa[4][4];
        #pragma unroll
        for (int s = 0; s < 4; s++) {
            pa[s][0] = f2h2(sc[2 * s][0], sc[2 * s][1]);
            pa[s][1] = f2h2(sc[2 * s][2], sc[2 * s][3]);
            pa[s][2] = f2h2(sc[2 * s + 1][0], sc[2 * s + 1][1]);
            pa[s][3] = f2h2(sc[2 * s + 1][2], sc[2 * s + 1][3]);
        }

        #pragma unroll
        for (int blk = 0; blk < 2; blk++) {
            #pragma unroll
            for (int nv = 0; nv < 16; nv++) {
                uint4 vv = *(const uint4*)&Vb[(8 * nv + grp) * PTC + 16 * blk + 4 * qid];
                mma_f16(of[nv], pa[2 * blk], vv.x, vv.y);
                mma_f16(of[nv], pa[2 * blk + 1], vv.z, vv.w);
            }
        }
    }

    float r0 = 1.f / l0, r1 = 1.f / l1;
    #pragma unroll
    for (int n = 0; n < 16; n++) {
        int row = q0 + wq + grp, col = 8 * n + 2 * qid;
        *(float2*)&g_O[(g * SQ + row) * VDIM + col]     =
            make_float2(of[n][0] * r0, of[n][1] * r0);
        *(float2*)&g_O[(g * SQ + row + 8) * VDIM + col] =
            make_float2(of[n][2] * r1, of[n][3] * r1);
    }
}

// ============================================================================
// Epilogue: warp per (s,h), 8 warps/block. x = O[2h]-lam*O[2h+1]; RMSNorm;
// * subg * (1-lam_init); store fp16 to g_Xh.
// ============================================================================
__global__ __launch_bounds__(256) void epi_kernel(const float* __restrict__ subg)
{
    const int wid  = threadIdx.x >> 5;
    const int lane = threadIdx.x & 31;
    const int idx  = blockIdx.x * 8 + wid;
    const int s = idx >> 4, h = idx & 15;
    const float lam = g_lam;

    float4 a = *(const float4*)&g_O[((2 * h) * SQ + s) * VDIM + lane * 4];
    float4 b = *(const float4*)&g_O[((2 * h + 1) * SQ + s) * VDIM + lane * 4];
    float x0 = a.x - lam * b.x, x1 = a.y - lam * b.y;
    float x2 = a.z - lam * b.z, x3 = a.w - lam * b.w;

    float v = x0 * x0 + x1 * x1 + x2 * x2 + x3 * x3;
    #pragma unroll
    for (int o = 16; o > 0; o >>= 1) v += __shfl_xor_sync(0xffffffffu, v, o);
    float rms = rsqrtf(v * (1.f / 128.f) + 1e-5f);

    float4 gm = *(const float4*)&subg[lane * 4];
    float scl = rms * (1.f - LAMBDA_INIT);
    *(uint2*)&g_Xh[s * ED + h * VDIM + lane * 4] = make_uint2(
        f2h2(x0 * gm.x * scl, x1 * gm.y * scl),
        f2h2(x2 * gm.z * scl, x3 * gm.w * scl));
}

// ============================================================================
// launch
// ============================================================================
extern "C" void kernel_launch(void* const* d_in, const int* in_sizes, int n_in,
                              void* d_out, int out_size)
{
    (void)in_sizes; (void)n_in; (void)out_size;
    const float* query = (const float*)d_in[0];
    const float* key   = (const float*)d_in[1];
    const float* value = (const float*)d_in[2];
    const unsigned char* mask = (const unsigned char*)d_in[4];
    const float* Wq  = (const float*)d_in[5];
    const float* Wk  = (const float*)d_in[6];
    const float* Wv  = (const float*)d_in[7];
    const float* Wo  = (const float*)d_in[8];
    const float* lq1 = (const float*)d_in[9];
    const float* lk1 = (const float*)d_in[10];
    const float* lq2 = (const float*)d_in[11];
    const float* lk2 = (const float*)d_in[12];
    const float* subg = (const float*)d_in[13];
    float* out = (float*)d_out;

    cudaFuncSetAttribute(attn_kernel, cudaFuncAttributeMaxDynamicSharedMemorySize, ATTN_SMEM);

    cvt_kernel<<<dim3(SQ * ED / 4 / 256, 7), 256>>>(query, key, value, Wq, Wk, Wv, Wo);
    gemm_nt<<<dim3(16, 16, 3), 256>>>(nullptr, 0, 0, 0, 1);  // fused Q,K,V projections
    attn_kernel<<<dim3(16, 32), 256, ATTN_SMEM>>>(mask);
    lam_kernel<<<1, 64>>>(lq1, lk1, lq2, lk2);
    epi_kernel<<<SQ * NH / 8, 256>>>(subg);
    gemm_nt<<<dim3(16, 16, 1), 256>>>(out, 3, 3, 0, 0);      // out = X * Wo
}